// round 1
// baseline (speedup 1.0000x reference)
#include <cuda_runtime.h>
#include <cuda_bf16.h>
#include <math.h>

// Problem constants
#define B_   32
#define TQ   256
#define TK   1024
#define D_   512
#define NH   4
#define PROJ 512
#define HP   (NH * PROJ)      // 2048
#define HD   (NH * D_)        // 2048
#define A_ELEMS ((long)NH * B_ * TQ * TK)   // 33554432

// Scratch (static device allocations are the sanctioned workaround)
__device__ float g_ms[(long)B_ * TQ * HP];      // 8192 x 2048
__device__ float g_mh[(long)B_ * TK * PROJ];    // 32768 x 512
__device__ float g_ctx[(long)B_ * TQ * HD];     // 8192 x 2048
__device__ float g_Wphi[(long)HP * D_];
__device__ float g_bphi[HP];
__device__ float g_Wpsi[(long)PROJ * D_];
__device__ float g_bpsi[PROJ];
__device__ float g_Wred[(long)D_ * HD];
__device__ float g_bred[D_];

// ---------------------------------------------------------------------------
// Fold BN into weights: Wf[o,d] = W[o,d]*scale[d]; bias[o] = sum_d W[o,d]*shift[d]
// scale = gamma * rsqrt(var+eps); shift = beta - mean*scale
// ---------------------------------------------------------------------------
__global__ void fold_kernel(const float* __restrict__ W,
                            const float* __restrict__ gamma,
                            const float* __restrict__ beta,
                            const float* __restrict__ mean,
                            const float* __restrict__ var,
                            float* __restrict__ Wf,
                            float* __restrict__ bias,
                            int D)
{
    int o = blockIdx.x;
    int tid = threadIdx.x;
    float partial = 0.f;
    const float* wrow = W + (long)o * D;
    float* wfrow = Wf + (long)o * D;
    for (int d = tid; d < D; d += blockDim.x) {
        float sc = gamma[d] * rsqrtf(var[d] + 1e-5f);
        float sh = beta[d] - mean[d] * sc;
        float w = wrow[d];
        wfrow[d] = w * sc;
        partial += w * sh;
    }
    __shared__ float red[256];
    red[tid] = partial;
    __syncthreads();
    for (int s = 128; s > 0; s >>= 1) {
        if (tid < s) red[tid] += red[tid + s];
        __syncthreads();
    }
    if (tid == 0) bias[o] = red[0];
}

// ---------------------------------------------------------------------------
// Tiled fp32 GEMM.  NT=true: C = A[M,K] * B[N,K]^T (+bias).  NT=false: C = A*B[K,N].
// Batched via blockIdx.z: z1 = z/zdiv, z2 = z%zdiv; pointer offsets z1*s1 + z2*s2.
// All dims assumed divisible by tile sizes (true for this problem).
// ---------------------------------------------------------------------------
#define BM 64
#define BN 64
#define BK 16

template <bool NT>
__global__ void __launch_bounds__(256)
gemm_kernel(const float* __restrict__ A, const float* __restrict__ Bm,
            const float* __restrict__ bias, float* __restrict__ C,
            int M, int N, int K, int lda, int ldb, int ldc,
            int zdiv, long a_s1, long a_s2, long b_s1, long b_s2,
            long c_s1, long c_s2)
{
    int z = blockIdx.z;
    int z1 = z / zdiv, z2 = z % zdiv;
    const float* Ab = A + z1 * a_s1 + z2 * a_s2;
    const float* Bb = Bm + z1 * b_s1 + z2 * b_s2;
    float* Cb = C + z1 * c_s1 + z2 * c_s2;

    __shared__ float As[BK][BM];
    __shared__ float Bs[BK][BN];

    int tid = threadIdx.x;
    int m0 = blockIdx.y * BM;
    int n0 = blockIdx.x * BN;

    // A loading: 64 rows x 16 cols, each thread loads one float4
    int lrow = tid >> 2;          // 0..63
    int lcol = (tid & 3) * 4;     // 0,4,8,12
    const float* Ag = Ab + (long)(m0 + lrow) * lda + lcol;

    // B loading
    const float* Bg;
    int br = 0, bc = 0;
    if (NT) {
        Bg = Bb + (long)(n0 + lrow) * ldb + lcol;
    } else {
        br = tid >> 4;            // k index 0..15
        bc = (tid & 15) * 4;      // n offset
        Bg = Bb + (long)br * ldb + n0 + bc;
    }

    int tx = tid & 15;            // micro-tile column (x4)
    int ty = tid >> 4;            // micro-tile row (x4)

    float acc[4][4];
#pragma unroll
    for (int i = 0; i < 4; i++)
#pragma unroll
        for (int j = 0; j < 4; j++) acc[i][j] = 0.f;

    for (int k0 = 0; k0 < K; k0 += BK) {
        float4 av = *(const float4*)(Ag + k0);
        float4 bv;
        if (NT) bv = *(const float4*)(Bg + k0);
        else    bv = *(const float4*)(Bg + (long)k0 * ldb);

        __syncthreads();
        As[lcol + 0][lrow] = av.x;
        As[lcol + 1][lrow] = av.y;
        As[lcol + 2][lrow] = av.z;
        As[lcol + 3][lrow] = av.w;
        if (NT) {
            Bs[lcol + 0][lrow] = bv.x;
            Bs[lcol + 1][lrow] = bv.y;
            Bs[lcol + 2][lrow] = bv.z;
            Bs[lcol + 3][lrow] = bv.w;
        } else {
            *(float4*)&Bs[br][bc] = bv;
        }
        __syncthreads();

#pragma unroll
        for (int k = 0; k < BK; k++) {
            float4 a4 = *(const float4*)&As[k][ty * 4];
            float4 b4 = *(const float4*)&Bs[k][tx * 4];
            float ar[4] = {a4.x, a4.y, a4.z, a4.w};
            float brg[4] = {b4.x, b4.y, b4.z, b4.w};
#pragma unroll
            for (int i = 0; i < 4; i++)
#pragma unroll
                for (int j = 0; j < 4; j++) acc[i][j] += ar[i] * brg[j];
        }
    }

    float4 bv4 = make_float4(0.f, 0.f, 0.f, 0.f);
    if (bias) bv4 = *(const float4*)(bias + n0 + tx * 4);
#pragma unroll
    for (int i = 0; i < 4; i++) {
        int mrow = m0 + ty * 4 + i;
        float4 v;
        v.x = acc[i][0] + bv4.x;
        v.y = acc[i][1] + bv4.y;
        v.z = acc[i][2] + bv4.z;
        v.w = acc[i][3] + bv4.w;
        *(float4*)(Cb + (long)mrow * ldc + n0 + tx * 4) = v;
    }
}

// ---------------------------------------------------------------------------
// Row softmax, in place. One block per row (1024 cols, 256 threads x 4 elems).
// ---------------------------------------------------------------------------
__global__ void __launch_bounds__(256)
softmax_kernel(float* __restrict__ a)
{
    float* row = a + (long)blockIdx.x * TK;
    int tid = threadIdx.x;
    float x[4];
    float mx = -INFINITY;
#pragma unroll
    for (int i = 0; i < 4; i++) {
        x[i] = row[tid + 256 * i];
        mx = fmaxf(mx, x[i]);
    }
    __shared__ float red[256];
    red[tid] = mx;
    __syncthreads();
    for (int s = 128; s > 0; s >>= 1) {
        if (tid < s) red[tid] = fmaxf(red[tid], red[tid + s]);
        __syncthreads();
    }
    mx = red[0];
    __syncthreads();
    float sum = 0.f;
#pragma unroll
    for (int i = 0; i < 4; i++) {
        x[i] = expf(x[i] - mx);
        sum += x[i];
    }
    red[tid] = sum;
    __syncthreads();
    for (int s = 128; s > 0; s >>= 1) {
        if (tid < s) red[tid] += red[tid + s];
        __syncthreads();
    }
    float inv = 1.f / red[0];
#pragma unroll
    for (int i = 0; i < 4; i++) row[tid + 256 * i] = x[i] * inv;
}

// ---------------------------------------------------------------------------
extern "C" void kernel_launch(void* const* d_in, const int* in_sizes, int n_in,
                              void* d_out, int out_size)
{
    const float* s_in      = (const float*)d_in[0];
    const float* h_in      = (const float*)d_in[1];
    const float* phi_gamma = (const float*)d_in[2];
    const float* phi_beta  = (const float*)d_in[3];
    const float* phi_mean  = (const float*)d_in[4];
    const float* phi_var   = (const float*)d_in[5];
    const float* W_phi     = (const float*)d_in[6];
    const float* psi_gamma = (const float*)d_in[7];
    const float* psi_beta  = (const float*)d_in[8];
    const float* psi_mean  = (const float*)d_in[9];
    const float* psi_var   = (const float*)d_in[10];
    const float* W_psi     = (const float*)d_in[11];
    const float* red_gamma = (const float*)d_in[12];
    const float* red_beta  = (const float*)d_in[13];
    const float* red_mean  = (const float*)d_in[14];
    const float* red_var   = (const float*)d_in[15];
    const float* W_red     = (const float*)d_in[16];

    float* a_out = (float*)d_out;             // [H, B, Tq, Tk]
    float* c_out = a_out + A_ELEMS;           // [B, Tq, D]

    float *ms, *mh, *ctx, *Wphi, *bphi, *Wpsi, *bpsi, *Wred, *bred;
    cudaGetSymbolAddress((void**)&ms,   g_ms);
    cudaGetSymbolAddress((void**)&mh,   g_mh);
    cudaGetSymbolAddress((void**)&ctx,  g_ctx);
    cudaGetSymbolAddress((void**)&Wphi, g_Wphi);
    cudaGetSymbolAddress((void**)&bphi, g_bphi);
    cudaGetSymbolAddress((void**)&Wpsi, g_Wpsi);
    cudaGetSymbolAddress((void**)&bpsi, g_bpsi);
    cudaGetSymbolAddress((void**)&Wred, g_Wred);
    cudaGetSymbolAddress((void**)&bred, g_bred);

    // 1. Fold BN into weights
    fold_kernel<<<HP, 256>>>(W_phi, phi_gamma, phi_beta, phi_mean, phi_var, Wphi, bphi, D_);
    fold_kernel<<<PROJ, 256>>>(W_psi, psi_gamma, psi_beta, psi_mean, psi_var, Wpsi, bpsi, D_);
    fold_kernel<<<D_, 256>>>(W_red, red_gamma, red_beta, red_mean, red_var, Wred, bred, HD);

    // 2. ms = s @ Wphi'^T + bphi : [8192, 2048], K=512
    gemm_kernel<true><<<dim3(HP / BN, (B_ * TQ) / BM, 1), 256>>>(
        s_in, Wphi, bphi, ms,
        B_ * TQ, HP, D_, D_, D_, HP,
        1, 0, 0, 0, 0, 0, 0);

    // 3. mh = h @ Wpsi'^T + bpsi : [32768, 512], K=512
    gemm_kernel<true><<<dim3(PROJ / BN, (B_ * TK) / BM, 1), 256>>>(
        h_in, Wpsi, bpsi, mh,
        B_ * TK, PROJ, D_, D_, D_, PROJ,
        1, 0, 0, 0, 0, 0, 0);

    // 4. scores e[h,b,q,k] = ms4[b,q,h,:] . mh[b,k,:]
    //    z = b*NH + hd; A offset = b*(TQ*HP) + hd*PROJ; B offset = b*(TK*PROJ);
    //    C offset = b*(TQ*TK) + hd*(B_*TQ*TK)
    gemm_kernel<true><<<dim3(TK / BN, TQ / BM, B_ * NH), 256>>>(
        ms, mh, nullptr, a_out,
        TQ, TK, PROJ, HP, PROJ, TK,
        NH,
        (long)TQ * HP, (long)PROJ,
        (long)TK * PROJ, 0L,
        (long)TQ * TK, (long)B_ * TQ * TK);

    // 5. softmax over last dim of a (in place): 128*256 rows of 1024
    softmax_kernel<<<NH * B_ * TQ, 256>>>(a_out);

    // 6. ctx[b,q,hd,:] = a[hd,b,q,:] @ h[b]   (NN GEMM)
    gemm_kernel<false><<<dim3(D_ / BN, TQ / BM, B_ * NH), 256>>>(
        a_out, h_in, nullptr, ctx,
        TQ, D_, TK, TK, D_, HD,
        NH,
        (long)TQ * TK, (long)B_ * TQ * TK,
        (long)TK * D_, 0L,
        (long)TQ * HD, (long)D_);

    // 7. c = ctx @ Wred'^T + bred : [8192, 512], K=2048
    gemm_kernel<true><<<dim3(D_ / BN, (B_ * TQ) / BM, 1), 256>>>(
        ctx, Wred, bred, c_out,
        B_ * TQ, D_, HD, HD, HD, D_,
        1, 0, 0, 0, 0, 0, 0);
}

// round 2
// speedup vs baseline: 1.4888x; 1.4888x over previous
#include <cuda_runtime.h>
#include <cuda_bf16.h>
#include <math.h>

// Problem constants
#define B_   32
#define TQ   256
#define TK   1024
#define D_   512
#define NH   4
#define PROJ 512
#define HP   (NH * PROJ)      // 2048
#define HD   (NH * D_)        // 2048
#define A_ELEMS ((long)NH * B_ * TQ * TK)   // 33554432

// Scratch (static device allocations are the sanctioned workaround)
__device__ float g_ms[(long)B_ * TQ * HP];      // 8192 x 2048
__device__ float g_mh[(long)B_ * TK * PROJ];    // 32768 x 512
__device__ float g_ctx[(long)B_ * TQ * HD];     // 8192 x 2048
__device__ float g_Wphi[(long)HP * D_];
__device__ float g_bphi[HP];
__device__ float g_Wpsi[(long)PROJ * D_];
__device__ float g_bpsi[PROJ];
__device__ float g_Wred[(long)D_ * HD];
__device__ float g_bred[D_];

// ---------------------------------------------------------------------------
// Fold BN into weights: Wf[o,d] = W[o,d]*scale[d]; bias[o] = sum_d W[o,d]*shift[d]
// ---------------------------------------------------------------------------
__global__ void fold_kernel(const float* __restrict__ W,
                            const float* __restrict__ gamma,
                            const float* __restrict__ beta,
                            const float* __restrict__ mean,
                            const float* __restrict__ var,
                            float* __restrict__ Wf,
                            float* __restrict__ bias,
                            int D)
{
    int o = blockIdx.x;
    int tid = threadIdx.x;
    float partial = 0.f;
    const float* wrow = W + (long)o * D;
    float* wfrow = Wf + (long)o * D;
    for (int d = tid; d < D; d += blockDim.x) {
        float sc = gamma[d] * rsqrtf(var[d] + 1e-5f);
        float sh = beta[d] - mean[d] * sc;
        float w = wrow[d];
        wfrow[d] = w * sc;
        partial += w * sh;
    }
    __shared__ float red[256];
    red[tid] = partial;
    __syncthreads();
    for (int s = 128; s > 0; s >>= 1) {
        if (tid < s) red[tid] += red[tid + s];
        __syncthreads();
    }
    if (tid == 0) bias[o] = red[0];
}

// ---------------------------------------------------------------------------
// Tiled fp32 GEMM, 128x128 CTA tile, 8x8 microtile, register-staged pipeline.
// NT=true: C = A[M,K] * B[N,K]^T (+bias).  NT=false: C = A[M,K]*B[K,N].
// Batched via blockIdx.z: z1 = z/zdiv, z2 = z%zdiv.
// All dims divisible by tile sizes for this problem.
// ---------------------------------------------------------------------------
#define BM 128
#define BN 128
#define BK 16
#define BMP (BM + 4)
#define BNP (BN + 4)

template <bool NT>
__global__ void __launch_bounds__(256, 2)
gemm_kernel(const float* __restrict__ A, const float* __restrict__ Bm,
            const float* __restrict__ bias, float* __restrict__ C,
            int M, int N, int K, int lda, int ldb, int ldc,
            int zdiv, long a_s1, long a_s2, long b_s1, long b_s2,
            long c_s1, long c_s2)
{
    int z = blockIdx.z;
    int z1 = z / zdiv, z2 = z % zdiv;
    const float* Ab = A + z1 * a_s1 + z2 * a_s2;
    const float* Bb = Bm + z1 * b_s1 + z2 * b_s2;
    float* Cb = C + z1 * c_s1 + z2 * c_s2;

    __shared__ float As[BK][BMP];
    __shared__ float Bs[BK][BNP];

    int tid = threadIdx.x;
    int tx = tid & 15;            // micro col (x4, two 64-strided halves)
    int ty = tid >> 4;            // micro row
    int m0 = blockIdx.y * BM;
    int n0 = blockIdx.x * BN;

    // A tile loading: 128 rows x 16 cols; each thread 2x float4
    int arow = tid >> 2;          // 0..63
    int acol = (tid & 3) * 4;     // 0,4,8,12
    const float* Ag0 = Ab + (long)(m0 + arow) * lda + acol;
    const float* Ag1 = Ab + (long)(m0 + arow + 64) * lda + acol;

    const float *Bg0, *Bg1;
    int bkrow = 0, bncol = 0;
    if (NT) {
        Bg0 = Bb + (long)(n0 + arow) * ldb + acol;
        Bg1 = Bb + (long)(n0 + arow + 64) * ldb + acol;
    } else {
        bkrow = tid >> 4;         // 0..15
        bncol = (tid & 15) * 4;   // 0..60
        Bg0 = Bb + (long)bkrow * ldb + n0 + bncol;
        Bg1 = Bg0 + 64;
    }

    float acc[8][8];
#pragma unroll
    for (int i = 0; i < 8; i++)
#pragma unroll
        for (int j = 0; j < 8; j++) acc[i][j] = 0.f;

    // prologue: stage tile 0
    float4 av0 = *(const float4*)Ag0;
    float4 av1 = *(const float4*)Ag1;
    float4 bv0 = *(const float4*)Bg0;
    float4 bv1 = *(const float4*)Bg1;

    for (int k0 = 0; k0 < K; k0 += BK) {
        __syncthreads();
        // store A (transpose into [k][m])
        As[acol + 0][arow] = av0.x;
        As[acol + 1][arow] = av0.y;
        As[acol + 2][arow] = av0.z;
        As[acol + 3][arow] = av0.w;
        As[acol + 0][arow + 64] = av1.x;
        As[acol + 1][arow + 64] = av1.y;
        As[acol + 2][arow + 64] = av1.z;
        As[acol + 3][arow + 64] = av1.w;
        if (NT) {
            Bs[acol + 0][arow] = bv0.x;
            Bs[acol + 1][arow] = bv0.y;
            Bs[acol + 2][arow] = bv0.z;
            Bs[acol + 3][arow] = bv0.w;
            Bs[acol + 0][arow + 64] = bv1.x;
            Bs[acol + 1][arow + 64] = bv1.y;
            Bs[acol + 2][arow + 64] = bv1.z;
            Bs[acol + 3][arow + 64] = bv1.w;
        } else {
            *(float4*)&Bs[bkrow][bncol] = bv0;
            *(float4*)&Bs[bkrow][bncol + 64] = bv1;
        }
        __syncthreads();

        // prefetch next tile into registers (overlaps with compute)
        if (k0 + BK < K) {
            Ag0 += BK; Ag1 += BK;
            av0 = *(const float4*)Ag0;
            av1 = *(const float4*)Ag1;
            if (NT) {
                Bg0 += BK; Bg1 += BK;
            } else {
                Bg0 += (long)BK * ldb; Bg1 += (long)BK * ldb;
            }
            bv0 = *(const float4*)Bg0;
            bv1 = *(const float4*)Bg1;
        }

#pragma unroll
        for (int k = 0; k < BK; k++) {
            float4 a0 = *(const float4*)&As[k][ty * 4];
            float4 a1 = *(const float4*)&As[k][ty * 4 + 64];
            float4 b0 = *(const float4*)&Bs[k][tx * 4];
            float4 b1 = *(const float4*)&Bs[k][tx * 4 + 64];
            float ar[8] = {a0.x, a0.y, a0.z, a0.w, a1.x, a1.y, a1.z, a1.w};
            float br[8] = {b0.x, b0.y, b0.z, b0.w, b1.x, b1.y, b1.z, b1.w};
#pragma unroll
            for (int i = 0; i < 8; i++)
#pragma unroll
                for (int j = 0; j < 8; j++) acc[i][j] += ar[i] * br[j];
        }
    }

    float4 bb0 = make_float4(0.f, 0.f, 0.f, 0.f);
    float4 bb1 = bb0;
    if (bias) {
        bb0 = *(const float4*)(bias + n0 + tx * 4);
        bb1 = *(const float4*)(bias + n0 + tx * 4 + 64);
    }
#pragma unroll
    for (int i = 0; i < 8; i++) {
        int mrow = m0 + ty * 4 + (i < 4 ? i : 60 + i);   // i>=4 -> +64
        float4 v0, v1;
        v0.x = acc[i][0] + bb0.x; v0.y = acc[i][1] + bb0.y;
        v0.z = acc[i][2] + bb0.z; v0.w = acc[i][3] + bb0.w;
        v1.x = acc[i][4] + bb1.x; v1.y = acc[i][5] + bb1.y;
        v1.z = acc[i][6] + bb1.z; v1.w = acc[i][7] + bb1.w;
        *(float4*)(Cb + (long)mrow * ldc + n0 + tx * 4) = v0;
        *(float4*)(Cb + (long)mrow * ldc + n0 + tx * 4 + 64) = v1;
    }
}

// ---------------------------------------------------------------------------
// Row softmax, in place. One block per row (1024 cols, 256 threads x 4 elems).
// ---------------------------------------------------------------------------
__global__ void __launch_bounds__(256)
softmax_kernel(float* __restrict__ a)
{
    float* row = a + (long)blockIdx.x * TK;
    int tid = threadIdx.x;
    float x[4];
    float mx = -INFINITY;
#pragma unroll
    for (int i = 0; i < 4; i++) {
        x[i] = row[tid + 256 * i];
        mx = fmaxf(mx, x[i]);
    }
    __shared__ float red[256];
    red[tid] = mx;
    __syncthreads();
    for (int s = 128; s > 0; s >>= 1) {
        if (tid < s) red[tid] = fmaxf(red[tid], red[tid + s]);
        __syncthreads();
    }
    mx = red[0];
    __syncthreads();
    float sum = 0.f;
#pragma unroll
    for (int i = 0; i < 4; i++) {
        x[i] = expf(x[i] - mx);
        sum += x[i];
    }
    red[tid] = sum;
    __syncthreads();
    for (int s = 128; s > 0; s >>= 1) {
        if (tid < s) red[tid] += red[tid + s];
        __syncthreads();
    }
    float inv = 1.f / red[0];
#pragma unroll
    for (int i = 0; i < 4; i++) row[tid + 256 * i] = x[i] * inv;
}

// ---------------------------------------------------------------------------
extern "C" void kernel_launch(void* const* d_in, const int* in_sizes, int n_in,
                              void* d_out, int out_size)
{
    const float* s_in      = (const float*)d_in[0];
    const float* h_in      = (const float*)d_in[1];
    const float* phi_gamma = (const float*)d_in[2];
    const float* phi_beta  = (const float*)d_in[3];
    const float* phi_mean  = (const float*)d_in[4];
    const float* phi_var   = (const float*)d_in[5];
    const float* W_phi     = (const float*)d_in[6];
    const float* psi_gamma = (const float*)d_in[7];
    const float* psi_beta  = (const float*)d_in[8];
    const float* psi_mean  = (const float*)d_in[9];
    const float* psi_var   = (const float*)d_in[10];
    const float* W_psi     = (const float*)d_in[11];
    const float* red_gamma = (const float*)d_in[12];
    const float* red_beta  = (const float*)d_in[13];
    const float* red_mean  = (const float*)d_in[14];
    const float* red_var   = (const float*)d_in[15];
    const float* W_red     = (const float*)d_in[16];

    float* a_out = (float*)d_out;             // [H, B, Tq, Tk]
    float* c_out = a_out + A_ELEMS;           // [B, Tq, D]

    float *ms, *mh, *ctx, *Wphi, *bphi, *Wpsi, *bpsi, *Wred, *bred;
    cudaGetSymbolAddress((void**)&ms,   g_ms);
    cudaGetSymbolAddress((void**)&mh,   g_mh);
    cudaGetSymbolAddress((void**)&ctx,  g_ctx);
    cudaGetSymbolAddress((void**)&Wphi, g_Wphi);
    cudaGetSymbolAddress((void**)&bphi, g_bphi);
    cudaGetSymbolAddress((void**)&Wpsi, g_Wpsi);
    cudaGetSymbolAddress((void**)&bpsi, g_bpsi);
    cudaGetSymbolAddress((void**)&Wred, g_Wred);
    cudaGetSymbolAddress((void**)&bred, g_bred);

    // 1. Fold BN into weights
    fold_kernel<<<HP, 256>>>(W_phi, phi_gamma, phi_beta, phi_mean, phi_var, Wphi, bphi, D_);
    fold_kernel<<<PROJ, 256>>>(W_psi, psi_gamma, psi_beta, psi_mean, psi_var, Wpsi, bpsi, D_);
    fold_kernel<<<D_, 256>>>(W_red, red_gamma, red_beta, red_mean, red_var, Wred, bred, HD);

    // 2. ms = s @ Wphi'^T + bphi : [8192, 2048], K=512
    gemm_kernel<true><<<dim3(HP / BN, (B_ * TQ) / BM, 1), 256>>>(
        s_in, Wphi, bphi, ms,
        B_ * TQ, HP, D_, D_, D_, HP,
        1, 0, 0, 0, 0, 0, 0);

    // 3. mh = h @ Wpsi'^T + bpsi : [32768, 512], K=512
    gemm_kernel<true><<<dim3(PROJ / BN, (B_ * TK) / BM, 1), 256>>>(
        h_in, Wpsi, bpsi, mh,
        B_ * TK, PROJ, D_, D_, D_, PROJ,
        1, 0, 0, 0, 0, 0, 0);

    // 4. scores e[h,b,q,k] = ms4[b,q,h,:] . mh[b,k,:]
    gemm_kernel<true><<<dim3(TK / BN, TQ / BM, B_ * NH), 256>>>(
        ms, mh, nullptr, a_out,
        TQ, TK, PROJ, HP, PROJ, TK,
        NH,
        (long)TQ * HP, (long)PROJ,
        (long)TK * PROJ, 0L,
        (long)TQ * TK, (long)B_ * TQ * TK);

    // 5. softmax over last dim of a (in place): 128*256 rows of 1024
    softmax_kernel<<<NH * B_ * TQ, 256>>>(a_out);

    // 6. ctx[b,q,hd,:] = a[hd,b,q,:] @ h[b]   (NN GEMM)
    gemm_kernel<false><<<dim3(D_ / BN, TQ / BM, B_ * NH), 256>>>(
        a_out, h_in, nullptr, ctx,
        TQ, D_, TK, TK, D_, HD,
        NH,
        (long)TQ * TK, (long)B_ * TQ * TK,
        (long)TK * D_, 0L,
        (long)TQ * HD, (long)D_);

    // 7. c = ctx @ Wred'^T + bred : [8192, 512], K=2048
    gemm_kernel<true><<<dim3(D_ / BN, (B_ * TQ) / BM, 1), 256>>>(
        ctx, Wred, bred, c_out,
        B_ * TQ, D_, HD, HD, HD, D_,
        1, 0, 0, 0, 0, 0, 0);
}

// round 4
// speedup vs baseline: 3.4451x; 2.3140x over previous
#include <cuda_runtime.h>
#include <cuda_bf16.h>
#include <math.h>
#include <stdint.h>

// Problem constants
#define B_   32
#define TQ   256
#define TK   1024
#define D_   512
#define NH   4
#define PROJ 512
#define HP   (NH * PROJ)      // 2048
#define HD   (NH * D_)        // 2048
#define A_ELEMS (4LL * 32 * 256 * 1024)   // 33554432

typedef long long ll;

// ---------------------------------------------------------------------------
// Scratch (static device arrays — sanctioned workaround for no-alloc rule)
// ---------------------------------------------------------------------------
__device__ __align__(128) __nv_bfloat16 g_s_hi[(size_t)B_ * TQ * D_];
__device__ __align__(128) __nv_bfloat16 g_s_lo[(size_t)B_ * TQ * D_];
__device__ __align__(128) __nv_bfloat16 g_h_hi[(size_t)B_ * TK * D_];
__device__ __align__(128) __nv_bfloat16 g_h_lo[(size_t)B_ * TK * D_];
__device__ __align__(128) __nv_bfloat16 g_ht_hi[(size_t)B_ * D_ * TK];
__device__ __align__(128) __nv_bfloat16 g_ht_lo[(size_t)B_ * D_ * TK];
__device__ __align__(128) __nv_bfloat16 g_ms_hi[(size_t)B_ * TQ * HP];
__device__ __align__(128) __nv_bfloat16 g_ms_lo[(size_t)B_ * TQ * HP];
__device__ __align__(128) __nv_bfloat16 g_mh_hi[(size_t)B_ * TK * PROJ];
__device__ __align__(128) __nv_bfloat16 g_mh_lo[(size_t)B_ * TK * PROJ];
__device__ __align__(128) __nv_bfloat16 g_a_hi[(size_t)A_ELEMS];
__device__ __align__(128) __nv_bfloat16 g_a_lo[(size_t)A_ELEMS];
__device__ __align__(128) __nv_bfloat16 g_ctx_hi[(size_t)B_ * TQ * HD];
__device__ __align__(128) __nv_bfloat16 g_ctx_lo[(size_t)B_ * TQ * HD];
__device__ __align__(128) __nv_bfloat16 g_Wphi_hi[(size_t)HP * D_];
__device__ __align__(128) __nv_bfloat16 g_Wphi_lo[(size_t)HP * D_];
__device__ __align__(128) __nv_bfloat16 g_Wpsi_hi[(size_t)PROJ * D_];
__device__ __align__(128) __nv_bfloat16 g_Wpsi_lo[(size_t)PROJ * D_];
__device__ __align__(128) __nv_bfloat16 g_Wred_hi[(size_t)D_ * HD];
__device__ __align__(128) __nv_bfloat16 g_Wred_lo[(size_t)D_ * HD];
__device__ float g_bphi[HP];
__device__ float g_bpsi[PROJ];
__device__ float g_bred[D_];

// ---------------------------------------------------------------------------
// Helpers
// ---------------------------------------------------------------------------
__device__ __forceinline__ uint32_t smem_to_u32(const void* p) {
    uint32_t a;
    asm("{ .reg .u64 t; cvta.to.shared.u64 t, %1; cvt.u32.u64 %0, t; }"
        : "=r"(a) : "l"(p));
    return a;
}

__device__ __forceinline__ void ldsm4(uint32_t addr, uint32_t& r0, uint32_t& r1,
                                      uint32_t& r2, uint32_t& r3)
{
    asm volatile("ldmatrix.sync.aligned.m8n8.x4.shared.b16 {%0,%1,%2,%3}, [%4];"
                 : "=r"(r0), "=r"(r1), "=r"(r2), "=r"(r3) : "r"(addr));
}

__device__ __forceinline__ void hmma(float* c, uint32_t a0, uint32_t a1,
                                     uint32_t a2, uint32_t a3,
                                     uint32_t b0, uint32_t b1)
{
    asm volatile(
        "mma.sync.aligned.m16n8k16.row.col.f32.bf16.bf16.f32 "
        "{%0,%1,%2,%3}, {%4,%5,%6,%7}, {%8,%9}, {%0,%1,%2,%3};"
        : "+f"(c[0]), "+f"(c[1]), "+f"(c[2]), "+f"(c[3])
        : "r"(a0), "r"(a1), "r"(a2), "r"(a3), "r"(b0), "r"(b1));
}

#define CP_ASYNC16(sa, ga) \
    asm volatile("cp.async.cg.shared.global [%0], [%1], 16;" :: "r"(sa), "l"(ga))
#define CP_COMMIT() asm volatile("cp.async.commit_group;" ::: "memory")
#define CP_WAIT1()  asm volatile("cp.async.wait_group 1;" ::: "memory")
#define CP_WAIT0()  asm volatile("cp.async.wait_group 0;" ::: "memory")

// ---------------------------------------------------------------------------
// smem layout: two stages of {Ahi, Alo, Bhi, Blo}, each tile 128 rows x 128B
// (SW128-swizzled). Epilogue reuses the same memory as a float staging pad.
// ---------------------------------------------------------------------------
#define TILE_SZ 16384          // 128 x 64 bf16 (128B rows)
#define STAGE_SZ (4 * TILE_SZ) // 64 KB
#define SMEM_TOTAL_GEMM (2 * STAGE_SZ)  // 131072
#define EP_PITCH 132

// Load one 128x64 bf16 tile (rows row0.., cols k0..k0+63) into swizzled smem.
__device__ __forceinline__ void tile_cp(const __nv_bfloat16* __restrict__ g,
                                        ll stride, ll row0, ll k0,
                                        uint32_t stile, int tid)
{
    int c = tid & 7;           // 16B chunk within row
    int r0 = tid >> 3;         // 0..31
    const char* gp = (const char*)(g + row0 * stride + k0 + c * 8);
    ll rb = stride * 2;
#pragma unroll
    for (int i = 0; i < 4; i++) {
        int r = r0 + i * 32;
        uint32_t sa = stile + (uint32_t)(r * 128) + (uint32_t)((c ^ (r & 7)) << 4);
        CP_ASYNC16(sa, gp + (ll)r * rb);
    }
}

// ---------------------------------------------------------------------------
// Split-bf16 tensor-core GEMM: C[M,N] = (Ahi+Alo)[M,K] @ (Bhi+Blo)[N,K]^T (+bias)
// 3-pass mma.sync (AhBh + AhBl + AlBh), fp32 accumulate.
// CTA tile 128x128, K chunks of 64, cp.async double buffering.
// Outputs: Cf (fp32) and/or Chi/Clo (bf16 split); either may be null.
// Batched via blockIdx.z (z1 = z/zdiv, z2 = z%zdiv).
// ---------------------------------------------------------------------------
__global__ void __launch_bounds__(256, 1)
gemm_tc(const __nv_bfloat16* __restrict__ Ahi, const __nv_bfloat16* __restrict__ Alo,
        const __nv_bfloat16* __restrict__ Bhi, const __nv_bfloat16* __restrict__ Blo,
        const float* __restrict__ bias,
        float* __restrict__ Cf, __nv_bfloat16* __restrict__ Chi, __nv_bfloat16* __restrict__ Clo,
        int K, ll lda, ll ldb, ll ldc,
        int zdiv, ll a_s1, ll a_s2, ll b_s1, ll b_s2, ll c_s1, ll c_s2)
{
    extern __shared__ char smem[];
    uint32_t sbase = smem_to_u32(smem);
    int tid = threadIdx.x;
    int lane = tid & 31;
    int wid = tid >> 5;
    int wm = wid & 1;          // M half (64 rows)
    int wn = wid >> 1;         // N quarter (32 cols)

    int z = blockIdx.z;
    int z1 = z / zdiv, z2 = z - z1 * zdiv;
    const __nv_bfloat16* Ah = Ahi + z1 * a_s1 + z2 * a_s2;
    const __nv_bfloat16* Al = Alo + z1 * a_s1 + z2 * a_s2;
    const __nv_bfloat16* Bh = Bhi + z1 * b_s1 + z2 * b_s2;
    const __nv_bfloat16* Bl = Blo + z1 * b_s1 + z2 * b_s2;
    ll m0 = (ll)blockIdx.y * 128;
    ll n0 = (ll)blockIdx.x * 128;
    ll coff = z1 * c_s1 + z2 * c_s2 + m0 * ldc + n0;

    // ldmatrix lane geometry
    int rl = lane & 7;
    int sub = lane >> 3;
    int rowA = (sub & 1) * 8 + rl;   // row within 16-row m-tile
    int jA = sub >> 1;               // k-chunk select (0/1)
    int rowB = (sub >> 1) * 8 + rl;  // row within 16-row n-pair
    int jB = sub & 1;

    uint32_t aRowOff[4], bRowOff[2];
#pragma unroll
    for (int mi = 0; mi < 4; mi++)
        aRowOff[mi] = (uint32_t)((wm * 64 + mi * 16 + rowA) * 128);
#pragma unroll
    for (int p = 0; p < 2; p++)
        bRowOff[p] = (uint32_t)((wn * 32 + p * 16 + rowB) * 128);

    float acc[4][4][4];
#pragma unroll
    for (int mi = 0; mi < 4; mi++)
#pragma unroll
        for (int ni = 0; ni < 4; ni++)
#pragma unroll
            for (int q = 0; q < 4; q++) acc[mi][ni][q] = 0.f;

    int C = K >> 6;

    // prologue: stage 0 and 1
    {
        uint32_t st = sbase;
        tile_cp(Ah, lda, m0, 0, st, tid);
        tile_cp(Al, lda, m0, 0, st + TILE_SZ, tid);
        tile_cp(Bh, ldb, n0, 0, st + 2 * TILE_SZ, tid);
        tile_cp(Bl, ldb, n0, 0, st + 3 * TILE_SZ, tid);
        CP_COMMIT();
    }
    if (C > 1) {
        uint32_t st = sbase + STAGE_SZ;
        tile_cp(Ah, lda, m0, 64, st, tid);
        tile_cp(Al, lda, m0, 64, st + TILE_SZ, tid);
        tile_cp(Bh, ldb, n0, 64, st + 2 * TILE_SZ, tid);
        tile_cp(Bl, ldb, n0, 64, st + 3 * TILE_SZ, tid);
        CP_COMMIT();
    }

    for (int c = 0; c < C; c++) {
        if (c < C - 1) CP_WAIT1(); else CP_WAIT0();
        __syncthreads();

        uint32_t st = sbase + (uint32_t)(c & 1) * STAGE_SZ;
#pragma unroll
        for (int kk = 0; kk < 4; kk++) {
            uint32_t chA = (uint32_t)(((kk * 2 + jA) ^ rl) << 4);
            uint32_t chB = (uint32_t)(((kk * 2 + jB) ^ rl) << 4);
            uint32_t ah[4][4], al[4][4];
#pragma unroll
            for (int mi = 0; mi < 4; mi++) {
                ldsm4(st + aRowOff[mi] + chA,
                      ah[mi][0], ah[mi][1], ah[mi][2], ah[mi][3]);
                ldsm4(st + TILE_SZ + aRowOff[mi] + chA,
                      al[mi][0], al[mi][1], al[mi][2], al[mi][3]);
            }
            uint32_t bh[4][2], bl[4][2];
#pragma unroll
            for (int p = 0; p < 2; p++) {
                uint32_t r0, r1, r2, r3;
                ldsm4(st + 2 * TILE_SZ + bRowOff[p] + chB, r0, r1, r2, r3);
                bh[2 * p][0] = r0; bh[2 * p][1] = r1;
                bh[2 * p + 1][0] = r2; bh[2 * p + 1][1] = r3;
                ldsm4(st + 3 * TILE_SZ + bRowOff[p] + chB, r0, r1, r2, r3);
                bl[2 * p][0] = r0; bl[2 * p][1] = r1;
                bl[2 * p + 1][0] = r2; bl[2 * p + 1][1] = r3;
            }
#pragma unroll
            for (int mi = 0; mi < 4; mi++)
#pragma unroll
                for (int ni = 0; ni < 4; ni++) {
                    hmma(acc[mi][ni], ah[mi][0], ah[mi][1], ah[mi][2], ah[mi][3],
                         bh[ni][0], bh[ni][1]);
                    hmma(acc[mi][ni], ah[mi][0], ah[mi][1], ah[mi][2], ah[mi][3],
                         bl[ni][0], bl[ni][1]);
                    hmma(acc[mi][ni], al[mi][0], al[mi][1], al[mi][2], al[mi][3],
                         bh[ni][0], bh[ni][1]);
                }
        }

        __syncthreads();
        if (c + 2 < C) {
            uint32_t stn = sbase + (uint32_t)(c & 1) * STAGE_SZ;
            ll k0 = (ll)(c + 2) * 64;
            tile_cp(Ah, lda, m0, k0, stn, tid);
            tile_cp(Al, lda, m0, k0, stn + TILE_SZ, tid);
            tile_cp(Bh, ldb, n0, k0, stn + 2 * TILE_SZ, tid);
            tile_cp(Bl, ldb, n0, k0, stn + 3 * TILE_SZ, tid);
            CP_COMMIT();
        }
    }

    // ---- Epilogue: acc -> smem staging -> coalesced global ----
    float* ep = (float*)smem;
    {
        int gr = lane >> 2, gc = lane & 3;
#pragma unroll
        for (int mi = 0; mi < 4; mi++)
#pragma unroll
            for (int ni = 0; ni < 4; ni++) {
                int row = wm * 64 + mi * 16 + gr;
                int col = wn * 32 + ni * 8 + gc * 2;
                float2 v0 = make_float2(acc[mi][ni][0], acc[mi][ni][1]);
                float2 v1 = make_float2(acc[mi][ni][2], acc[mi][ni][3]);
                *(float2*)&ep[row * EP_PITCH + col] = v0;
                *(float2*)&ep[(row + 8) * EP_PITCH + col] = v1;
            }
    }
    __syncthreads();

    {
        int lc = tid & 31;        // col group (x4)
        int rbase = tid >> 5;     // 0..7
        float4 bv = make_float4(0.f, 0.f, 0.f, 0.f);
        if (bias) bv = *(const float4*)(bias + n0 + lc * 4);
#pragma unroll
        for (int i = 0; i < 16; i++) {
            int row = rbase + i * 8;
            float4 v = *(float4*)&ep[row * EP_PITCH + lc * 4];
            v.x += bv.x; v.y += bv.y; v.z += bv.z; v.w += bv.w;
            ll off = coff + (ll)row * ldc + lc * 4;
            if (Cf) *(float4*)(Cf + off) = v;
            if (Chi) {
                __nv_bfloat16 h0 = __float2bfloat16(v.x);
                __nv_bfloat16 h1 = __float2bfloat16(v.y);
                __nv_bfloat16 h2 = __float2bfloat16(v.z);
                __nv_bfloat16 h3 = __float2bfloat16(v.w);
                __nv_bfloat16 l0 = __float2bfloat16(v.x - __bfloat162float(h0));
                __nv_bfloat16 l1 = __float2bfloat16(v.y - __bfloat162float(h1));
                __nv_bfloat16 l2 = __float2bfloat16(v.z - __bfloat162float(h2));
                __nv_bfloat16 l3 = __float2bfloat16(v.w - __bfloat162float(h3));
                uint2 hv, lv;
                __nv_bfloat16* hp = (__nv_bfloat16*)&hv;
                __nv_bfloat16* lp = (__nv_bfloat16*)&lv;
                hp[0] = h0; hp[1] = h1; hp[2] = h2; hp[3] = h3;
                lp[0] = l0; lp[1] = l1; lp[2] = l2; lp[3] = l3;
                *(uint2*)(Chi + off) = hv;
                *(uint2*)(Clo + off) = lv;
            }
        }
    }
}

// ---------------------------------------------------------------------------
// Fold BN into weights, output split bf16: Wf = W*scale, bias = W . shift
// ---------------------------------------------------------------------------
__global__ void fold_kernel(const float* __restrict__ W,
                            const float* __restrict__ gamma,
                            const float* __restrict__ beta,
                            const float* __restrict__ mean,
                            const float* __restrict__ var,
                            __nv_bfloat16* __restrict__ Whi,
                            __nv_bfloat16* __restrict__ Wlo,
                            float* __restrict__ bias, int D)
{
    int o = blockIdx.x;
    int tid = threadIdx.x;
    float partial = 0.f;
    const float* wrow = W + (ll)o * D;
    __nv_bfloat16* whr = Whi + (ll)o * D;
    __nv_bfloat16* wlr = Wlo + (ll)o * D;
    for (int d = tid; d < D; d += blockDim.x) {
        float sc = gamma[d] * rsqrtf(var[d] + 1e-5f);
        float sh = beta[d] - mean[d] * sc;
        float w = wrow[d];
        float wf = w * sc;
        __nv_bfloat16 hi = __float2bfloat16(wf);
        whr[d] = hi;
        wlr[d] = __float2bfloat16(wf - __bfloat162float(hi));
        partial += w * sh;
    }
    __shared__ float red[256];
    red[tid] = partial;
    __syncthreads();
    for (int s = 128; s > 0; s >>= 1) {
        if (tid < s) red[tid] += red[tid + s];
        __syncthreads();
    }
    if (tid == 0) bias[o] = red[0];
}

// ---------------------------------------------------------------------------
// Elementwise fp32 -> bf16 hi/lo split
// ---------------------------------------------------------------------------
__global__ void __launch_bounds__(256)
split_kernel(const float* __restrict__ x, __nv_bfloat16* __restrict__ hi,
             __nv_bfloat16* __restrict__ lo, ll n4)
{
    ll i = (ll)blockIdx.x * 256 + threadIdx.x;
    if (i >= n4) return;
    float4 v = *(const float4*)(x + i * 4);
    __nv_bfloat16 h0 = __float2bfloat16(v.x);
    __nv_bfloat16 h1 = __float2bfloat16(v.y);
    __nv_bfloat16 h2 = __float2bfloat16(v.z);
    __nv_bfloat16 h3 = __float2bfloat16(v.w);
    uint2 hv, lv;
    __nv_bfloat16* hp = (__nv_bfloat16*)&hv;
    __nv_bfloat16* lp = (__nv_bfloat16*)&lv;
    hp[0] = h0; hp[1] = h1; hp[2] = h2; hp[3] = h3;
    lp[0] = __float2bfloat16(v.x - __bfloat162float(h0));
    lp[1] = __float2bfloat16(v.y - __bfloat162float(h1));
    lp[2] = __float2bfloat16(v.z - __bfloat162float(h2));
    lp[3] = __float2bfloat16(v.w - __bfloat162float(h3));
    *(uint2*)(hi + i * 4) = hv;
    *(uint2*)(lo + i * 4) = lv;
}

// ---------------------------------------------------------------------------
// Per-batch transpose of h: ht[b][d][k] = h[b][k][d], split to bf16 hi/lo.
// ---------------------------------------------------------------------------
__global__ void __launch_bounds__(256)
transpose_split(const float* __restrict__ h, __nv_bfloat16* __restrict__ thi,
                __nv_bfloat16* __restrict__ tlo)
{
    __shared__ float t[32][33];
    int b = blockIdx.z;
    int k0 = blockIdx.x * 32;
    int d0 = blockIdx.y * 32;
    const float* hb = h + (ll)b * TK * D_;
#pragma unroll
    for (int j = 0; j < 4; j++) {
        int k = threadIdx.y + j * 8;
        t[k][threadIdx.x] = hb[(ll)(k0 + k) * D_ + d0 + threadIdx.x];
    }
    __syncthreads();
    __nv_bfloat16* th = thi + (ll)b * D_ * TK;
    __nv_bfloat16* tl = tlo + (ll)b * D_ * TK;
#pragma unroll
    for (int j = 0; j < 4; j++) {
        int d = threadIdx.y + j * 8;
        float v = t[threadIdx.x][d];
        __nv_bfloat16 hi = __float2bfloat16(v);
        ll off = (ll)(d0 + d) * TK + k0 + threadIdx.x;
        th[off] = hi;
        tl[off] = __float2bfloat16(v - __bfloat162float(hi));
    }
}

// ---------------------------------------------------------------------------
// Row softmax in place + dual write of bf16 hi/lo split.
// ---------------------------------------------------------------------------
__global__ void __launch_bounds__(256)
softmax_kernel(float* __restrict__ a, __nv_bfloat16* __restrict__ ahi,
               __nv_bfloat16* __restrict__ alo)
{
    ll rbase = (ll)blockIdx.x * TK;
    float* row = a + rbase;
    int tid = threadIdx.x;
    float x[4];
    float mx = -INFINITY;
#pragma unroll
    for (int i = 0; i < 4; i++) {
        x[i] = row[tid + 256 * i];
        mx = fmaxf(mx, x[i]);
    }
    __shared__ float red[256];
    red[tid] = mx;
    __syncthreads();
    for (int s = 128; s > 0; s >>= 1) {
        if (tid < s) red[tid] = fmaxf(red[tid], red[tid + s]);
        __syncthreads();
    }
    mx = red[0];
    __syncthreads();
    float sum = 0.f;
#pragma unroll
    for (int i = 0; i < 4; i++) {
        x[i] = expf(x[i] - mx);
        sum += x[i];
    }
    red[tid] = sum;
    __syncthreads();
    for (int s = 128; s > 0; s >>= 1) {
        if (tid < s) red[tid] += red[tid + s];
        __syncthreads();
    }
    float inv = 1.f / red[0];
#pragma unroll
    for (int i = 0; i < 4; i++) {
        float p = x[i] * inv;
        row[tid + 256 * i] = p;
        __nv_bfloat16 hi = __float2bfloat16(p);
        ahi[rbase + tid + 256 * i] = hi;
        alo[rbase + tid + 256 * i] = __float2bfloat16(p - __bfloat162float(hi));
    }
}

// ---------------------------------------------------------------------------
extern "C" void kernel_launch(void* const* d_in, const int* in_sizes, int n_in,
                              void* d_out, int out_size)
{
    const float* s_in      = (const float*)d_in[0];
    const float* h_in      = (const float*)d_in[1];
    const float* phi_gamma = (const float*)d_in[2];
    const float* phi_beta  = (const float*)d_in[3];
    const float* phi_mean  = (const float*)d_in[4];
    const float* phi_var   = (const float*)d_in[5];
    const float* W_phi     = (const float*)d_in[6];
    const float* psi_gamma = (const float*)d_in[7];
    const float* psi_beta  = (const float*)d_in[8];
    const float* psi_mean  = (const float*)d_in[9];
    const float* psi_var   = (const float*)d_in[10];
    const float* W_psi     = (const float*)d_in[11];
    const float* red_gamma = (const float*)d_in[12];
    const float* red_beta  = (const float*)d_in[13];
    const float* red_mean  = (const float*)d_in[14];
    const float* red_var   = (const float*)d_in[15];
    const float* W_red     = (const float*)d_in[16];

    float* a_out = (float*)d_out;               // [H, B, Tq, Tk]
    float* c_out = a_out + A_ELEMS;             // [B, Tq, D]

    __nv_bfloat16 *s_hi, *s_lo, *h_hi, *h_lo, *ht_hi, *ht_lo;
    __nv_bfloat16 *ms_hi, *ms_lo, *mh_hi, *mh_lo, *a_hi, *a_lo, *ctx_hi, *ctx_lo;
    __nv_bfloat16 *Wphi_hi, *Wphi_lo, *Wpsi_hi, *Wpsi_lo, *Wred_hi, *Wred_lo;
    float *bphi, *bpsi, *bred;
    cudaGetSymbolAddress((void**)&s_hi, g_s_hi);   cudaGetSymbolAddress((void**)&s_lo, g_s_lo);
    cudaGetSymbolAddress((void**)&h_hi, g_h_hi);   cudaGetSymbolAddress((void**)&h_lo, g_h_lo);
    cudaGetSymbolAddress((void**)&ht_hi, g_ht_hi); cudaGetSymbolAddress((void**)&ht_lo, g_ht_lo);
    cudaGetSymbolAddress((void**)&ms_hi, g_ms_hi); cudaGetSymbolAddress((void**)&ms_lo, g_ms_lo);
    cudaGetSymbolAddress((void**)&mh_hi, g_mh_hi); cudaGetSymbolAddress((void**)&mh_lo, g_mh_lo);
    cudaGetSymbolAddress((void**)&a_hi, g_a_hi);   cudaGetSymbolAddress((void**)&a_lo, g_a_lo);
    cudaGetSymbolAddress((void**)&ctx_hi, g_ctx_hi); cudaGetSymbolAddress((void**)&ctx_lo, g_ctx_lo);
    cudaGetSymbolAddress((void**)&Wphi_hi, g_Wphi_hi); cudaGetSymbolAddress((void**)&Wphi_lo, g_Wphi_lo);
    cudaGetSymbolAddress((void**)&Wpsi_hi, g_Wpsi_hi); cudaGetSymbolAddress((void**)&Wpsi_lo, g_Wpsi_lo);
    cudaGetSymbolAddress((void**)&Wred_hi, g_Wred_hi); cudaGetSymbolAddress((void**)&Wred_lo, g_Wred_lo);
    cudaGetSymbolAddress((void**)&bphi, g_bphi);
    cudaGetSymbolAddress((void**)&bpsi, g_bpsi);
    cudaGetSymbolAddress((void**)&bred, g_bred);

    cudaFuncSetAttribute(gemm_tc, cudaFuncAttributeMaxDynamicSharedMemorySize,
                         SMEM_TOTAL_GEMM);

    // 1. BN folding (split bf16 weights) + input conversions
    fold_kernel<<<HP, 256>>>(W_phi, phi_gamma, phi_beta, phi_mean, phi_var,
                             Wphi_hi, Wphi_lo, bphi, D_);
    fold_kernel<<<PROJ, 256>>>(W_psi, psi_gamma, psi_beta, psi_mean, psi_var,
                               Wpsi_hi, Wpsi_lo, bpsi, D_);
    fold_kernel<<<D_, 256>>>(W_red, red_gamma, red_beta, red_mean, red_var,
                             Wred_hi, Wred_lo, bred, HD);
    split_kernel<<<(int)(((ll)B_ * TQ * D_ / 4 + 255) / 256), 256>>>(
        s_in, s_hi, s_lo, (ll)B_ * TQ * D_ / 4);
    split_kernel<<<(int)(((ll)B_ * TK * D_ / 4 + 255) / 256), 256>>>(
        h_in, h_hi, h_lo, (ll)B_ * TK * D_ / 4);
    transpose_split<<<dim3(TK / 32, D_ / 32, B_), dim3(32, 8)>>>(h_in, ht_hi, ht_lo);

    // 2. ms = s @ Wphi^T + bphi  (M=8192, N=2048, K=512) -> split out
    gemm_tc<<<dim3(HP / 128, (B_ * TQ) / 128, 1), 256, SMEM_TOTAL_GEMM>>>(
        s_hi, s_lo, Wphi_hi, Wphi_lo, bphi,
        nullptr, ms_hi, ms_lo,
        D_, D_, D_, HP,
        1, 0, 0, 0, 0, 0, 0);

    // 3. mh = h @ Wpsi^T + bpsi  (M=32768, N=512, K=512) -> split out
    gemm_tc<<<dim3(PROJ / 128, (B_ * TK) / 128, 1), 256, SMEM_TOTAL_GEMM>>>(
        h_hi, h_lo, Wpsi_hi, Wpsi_lo, bpsi,
        nullptr, mh_hi, mh_lo,
        D_, D_, D_, PROJ,
        1, 0, 0, 0, 0, 0, 0);

    // 4. logits e[h,b,q,k] = ms4[b,q,h,:] . mh[b,k,:]  -> fp32 into a_out
    gemm_tc<<<dim3(TK / 128, TQ / 128, B_ * NH), 256, SMEM_TOTAL_GEMM>>>(
        ms_hi, ms_lo, mh_hi, mh_lo, nullptr,
        a_out, nullptr, nullptr,
        PROJ, HP, PROJ, TK,
        NH,
        (ll)TQ * HP, (ll)PROJ,
        (ll)TK * PROJ, 0,
        (ll)TQ * TK, (ll)B_ * TQ * TK);

    // 5. softmax (in place) + split bf16 write
    softmax_kernel<<<NH * B_ * TQ, 256>>>(a_out, a_hi, a_lo);

    // 6. ctx[b,q,h*D+d] = a[h,b,q,:] . ht[b,d,:]  (NT via transposed h) -> split out
    gemm_tc<<<dim3(D_ / 128, TQ / 128, B_ * NH), 256, SMEM_TOTAL_GEMM>>>(
        a_hi, a_lo, ht_hi, ht_lo, nullptr,
        nullptr, ctx_hi, ctx_lo,
        TK, TK, TK, HD,
        NH,
        (ll)TQ * TK, (ll)B_ * TQ * TK,
        (ll)D_ * TK, 0,
        (ll)TQ * HD, (ll)D_);

    // 7. c = ctx @ Wred^T + bred  (M=8192, N=512, K=2048) -> fp32 out
    gemm_tc<<<dim3(D_ / 128, (B_ * TQ) / 128, 1), 256, SMEM_TOTAL_GEMM>>>(
        ctx_hi, ctx_lo, Wred_hi, Wred_lo, bred,
        c_out, nullptr, nullptr,
        HD, HD, HD, D_,
        1, 0, 0, 0, 0, 0, 0);
}

// round 5
// speedup vs baseline: 4.0079x; 1.1634x over previous
#include <cuda_runtime.h>
#include <cuda_bf16.h>
#include <cuda_fp16.h>
#include <math.h>
#include <stdint.h>

// Problem constants
#define B_   32
#define TQ   256
#define TK   1024
#define D_   512
#define NH   4
#define PROJ 512
#define HP   (NH * PROJ)      // 2048
#define HD   (NH * D_)        // 2048
#define A_ELEMS (4LL * 32 * 256 * 1024)   // 33554432

typedef long long ll;

// ---------------------------------------------------------------------------
// Scratch (static device arrays — sanctioned workaround for no-alloc rule)
// ---------------------------------------------------------------------------
__device__ __align__(128) __nv_bfloat16 g_s_hi[(size_t)B_ * TQ * D_];
__device__ __align__(128) __nv_bfloat16 g_s_lo[(size_t)B_ * TQ * D_];
__device__ __align__(128) __nv_bfloat16 g_h_hi[(size_t)B_ * TK * D_];
__device__ __align__(128) __nv_bfloat16 g_h_lo[(size_t)B_ * TK * D_];
__device__ __align__(128) __half        g_ht_f16[(size_t)B_ * D_ * TK];
__device__ __align__(128) __nv_bfloat16 g_ms_hi[(size_t)B_ * TQ * HP];
__device__ __align__(128) __nv_bfloat16 g_ms_lo[(size_t)B_ * TQ * HP];
__device__ __align__(128) __nv_bfloat16 g_mh_hi[(size_t)B_ * TK * PROJ];
__device__ __align__(128) __nv_bfloat16 g_mh_lo[(size_t)B_ * TK * PROJ];
__device__ __align__(128) __half        g_a_f16[(size_t)A_ELEMS];
__device__ __align__(128) __nv_bfloat16 g_ctx_hi[(size_t)B_ * TQ * HD];
__device__ __align__(128) __nv_bfloat16 g_ctx_lo[(size_t)B_ * TQ * HD];
__device__ __align__(128) __nv_bfloat16 g_Wphi_hi[(size_t)HP * D_];
__device__ __align__(128) __nv_bfloat16 g_Wphi_lo[(size_t)HP * D_];
__device__ __align__(128) __nv_bfloat16 g_Wpsi_hi[(size_t)PROJ * D_];
__device__ __align__(128) __nv_bfloat16 g_Wpsi_lo[(size_t)PROJ * D_];
__device__ __align__(128) __nv_bfloat16 g_Wred_hi[(size_t)D_ * HD];
__device__ __align__(128) __nv_bfloat16 g_Wred_lo[(size_t)D_ * HD];
__device__ float g_bphi[HP];
__device__ float g_bpsi[PROJ];
__device__ float g_bred[D_];

// ---------------------------------------------------------------------------
// Helpers
// ---------------------------------------------------------------------------
__device__ __forceinline__ uint32_t smem_to_u32(const void* p) {
    uint32_t a;
    asm("{ .reg .u64 t; cvta.to.shared.u64 t, %1; cvt.u32.u64 %0, t; }"
        : "=r"(a) : "l"(p));
    return a;
}

__device__ __forceinline__ void ldsm4(uint32_t addr, uint32_t& r0, uint32_t& r1,
                                      uint32_t& r2, uint32_t& r3)
{
    asm volatile("ldmatrix.sync.aligned.m8n8.x4.shared.b16 {%0,%1,%2,%3}, [%4];"
                 : "=r"(r0), "=r"(r1), "=r"(r2), "=r"(r3) : "r"(addr));
}

__device__ __forceinline__ void hmma_bf16(float* c, uint32_t a0, uint32_t a1,
                                          uint32_t a2, uint32_t a3,
                                          uint32_t b0, uint32_t b1)
{
    asm volatile(
        "mma.sync.aligned.m16n8k16.row.col.f32.bf16.bf16.f32 "
        "{%0,%1,%2,%3}, {%4,%5,%6,%7}, {%8,%9}, {%0,%1,%2,%3};"
        : "+f"(c[0]), "+f"(c[1]), "+f"(c[2]), "+f"(c[3])
        : "r"(a0), "r"(a1), "r"(a2), "r"(a3), "r"(b0), "r"(b1));
}

__device__ __forceinline__ void hmma_fp16(float* c, uint32_t a0, uint32_t a1,
                                          uint32_t a2, uint32_t a3,
                                          uint32_t b0, uint32_t b1)
{
    asm volatile(
        "mma.sync.aligned.m16n8k16.row.col.f32.f16.f16.f32 "
        "{%0,%1,%2,%3}, {%4,%5,%6,%7}, {%8,%9}, {%0,%1,%2,%3};"
        : "+f"(c[0]), "+f"(c[1]), "+f"(c[2]), "+f"(c[3])
        : "r"(a0), "r"(a1), "r"(a2), "r"(a3), "r"(b0), "r"(b1));
}

#define CP_ASYNC16(sa, ga) \
    asm volatile("cp.async.cg.shared.global [%0], [%1], 16;" :: "r"(sa), "l"(ga))
#define CP_COMMIT() asm volatile("cp.async.commit_group;" ::: "memory")
#define CP_WAIT1()  asm volatile("cp.async.wait_group 1;" ::: "memory")
#define CP_WAIT0()  asm volatile("cp.async.wait_group 0;" ::: "memory")

// ---------------------------------------------------------------------------
// smem: MODE 0 (3-pass bf16 pairs): 2 stages x {Ahi,Alo,Bhi,Blo} = 128 KB
//       MODE 1 (1-pass fp16):       2 stages x {A,B} = 64 KB (+epilogue pad)
// Tiles are 128 rows x 128 B, SW128-swizzled. Epilogue reuses smem as fp32 pad.
// ---------------------------------------------------------------------------
#define TILE_SZ 16384
#define EP_PITCH 132
#define SMEM_MODE0 (8 * TILE_SZ)           // 131072
#define SMEM_MODE1 (128 * EP_PITCH * 4)    // 67584 (>= 4*TILE_SZ)

// Load one 128x64 bf16/fp16 tile (rows row0.., cols k0..k0+63) into swizzled smem.
__device__ __forceinline__ void tile_cp(const __nv_bfloat16* __restrict__ g,
                                        ll stride, ll row0, ll k0,
                                        uint32_t stile, int tid)
{
    int c = tid & 7;           // 16B chunk within row
    int r0 = tid >> 3;         // 0..31
    const char* gp = (const char*)(g + row0 * stride + k0 + c * 8);
    ll rb = stride * 2;
#pragma unroll
    for (int i = 0; i < 4; i++) {
        int r = r0 + i * 32;
        uint32_t sa = stile + (uint32_t)(r * 128) + (uint32_t)((c ^ (r & 7)) << 4);
        CP_ASYNC16(sa, gp + (ll)r * rb);
    }
}

// ---------------------------------------------------------------------------
// Tensor-core GEMM: C[M,N] = A[M,K] @ B[N,K]^T (+bias)
// MODE 0: split-bf16 3-pass (AhBh + AhBl + AlBh), fp32 accumulate.
// MODE 1: single-pass fp16 (Ahi/Bhi carry fp16 bits; Alo/Blo ignored).
// CTA tile 128x128, K chunks of 64, cp.async double buffering.
// Outputs: Cf (fp32) and/or Chi/Clo (bf16 split); either may be null.
// Batched via blockIdx.z (z1 = z/zdiv, z2 = z%zdiv).
// ---------------------------------------------------------------------------
template <int MODE>
__global__ void __launch_bounds__(256)
gemm_tc(const __nv_bfloat16* __restrict__ Ahi, const __nv_bfloat16* __restrict__ Alo,
        const __nv_bfloat16* __restrict__ Bhi, const __nv_bfloat16* __restrict__ Blo,
        const float* __restrict__ bias,
        float* __restrict__ Cf, __nv_bfloat16* __restrict__ Chi, __nv_bfloat16* __restrict__ Clo,
        int K, ll lda, ll ldb, ll ldc,
        int zdiv, ll a_s1, ll a_s2, ll b_s1, ll b_s2, ll c_s1, ll c_s2)
{
    extern __shared__ char smem[];
    uint32_t sbase = smem_to_u32(smem);
    int tid = threadIdx.x;
    int lane = tid & 31;
    int wid = tid >> 5;
    int wm = wid & 1;          // M half (64 rows)
    int wn = wid >> 1;         // N quarter (32 cols)

    constexpr uint32_t NT_TILES = (MODE == 0) ? 4u : 2u;
    constexpr uint32_t STG = NT_TILES * TILE_SZ;
    constexpr uint32_t B_OFF = (MODE == 0) ? 2u * TILE_SZ : TILE_SZ;

    int z = blockIdx.z;
    int z1 = z / zdiv, z2 = z - z1 * zdiv;
    const __nv_bfloat16* Ah = Ahi + z1 * a_s1 + z2 * a_s2;
    const __nv_bfloat16* Al = (MODE == 0) ? Alo + z1 * a_s1 + z2 * a_s2 : nullptr;
    const __nv_bfloat16* Bh = Bhi + z1 * b_s1 + z2 * b_s2;
    const __nv_bfloat16* Bl = (MODE == 0) ? Blo + z1 * b_s1 + z2 * b_s2 : nullptr;
    ll m0 = (ll)blockIdx.y * 128;
    ll n0 = (ll)blockIdx.x * 128;
    ll coff = z1 * c_s1 + z2 * c_s2 + m0 * ldc + n0;

    // ldmatrix lane geometry
    int rl = lane & 7;
    int sub = lane >> 3;
    int rowA = (sub & 1) * 8 + rl;   // row within 16-row m-tile
    int jA = sub >> 1;               // k-chunk select (0/1)
    int rowB = (sub >> 1) * 8 + rl;  // row within 16-row n-pair
    int jB = sub & 1;

    uint32_t aRowOff[4], bRowOff[2];
#pragma unroll
    for (int mi = 0; mi < 4; mi++)
        aRowOff[mi] = (uint32_t)((wm * 64 + mi * 16 + rowA) * 128);
#pragma unroll
    for (int p = 0; p < 2; p++)
        bRowOff[p] = (uint32_t)((wn * 32 + p * 16 + rowB) * 128);

    float acc[4][4][4];
#pragma unroll
    for (int mi = 0; mi < 4; mi++)
#pragma unroll
        for (int ni = 0; ni < 4; ni++)
#pragma unroll
            for (int q = 0; q < 4; q++) acc[mi][ni][q] = 0.f;

    int C = K >> 6;

    // prologue: stage 0 and 1
    {
        uint32_t st = sbase;
        tile_cp(Ah, lda, m0, 0, st, tid);
        tile_cp(Bh, ldb, n0, 0, st + B_OFF, tid);
        if (MODE == 0) {
            tile_cp(Al, lda, m0, 0, st + TILE_SZ, tid);
            tile_cp(Bl, ldb, n0, 0, st + 3 * TILE_SZ, tid);
        }
        CP_COMMIT();
    }
    if (C > 1) {
        uint32_t st = sbase + STG;
        tile_cp(Ah, lda, m0, 64, st, tid);
        tile_cp(Bh, ldb, n0, 64, st + B_OFF, tid);
        if (MODE == 0) {
            tile_cp(Al, lda, m0, 64, st + TILE_SZ, tid);
            tile_cp(Bl, ldb, n0, 64, st + 3 * TILE_SZ, tid);
        }
        CP_COMMIT();
    }

    for (int c = 0; c < C; c++) {
        if (c < C - 1) CP_WAIT1(); else CP_WAIT0();
        __syncthreads();

        uint32_t st = sbase + (uint32_t)(c & 1) * STG;
#pragma unroll
        for (int kk = 0; kk < 4; kk++) {
            uint32_t chA = (uint32_t)(((kk * 2 + jA) ^ rl) << 4);
            uint32_t chB = (uint32_t)(((kk * 2 + jB) ^ rl) << 4);
            if (MODE == 0) {
                uint32_t ah[4][4], al[4][4];
#pragma unroll
                for (int mi = 0; mi < 4; mi++) {
                    ldsm4(st + aRowOff[mi] + chA,
                          ah[mi][0], ah[mi][1], ah[mi][2], ah[mi][3]);
                    ldsm4(st + TILE_SZ + aRowOff[mi] + chA,
                          al[mi][0], al[mi][1], al[mi][2], al[mi][3]);
                }
                uint32_t bh[4][2], bl[4][2];
#pragma unroll
                for (int p = 0; p < 2; p++) {
                    uint32_t r0, r1, r2, r3;
                    ldsm4(st + 2 * TILE_SZ + bRowOff[p] + chB, r0, r1, r2, r3);
                    bh[2 * p][0] = r0; bh[2 * p][1] = r1;
                    bh[2 * p + 1][0] = r2; bh[2 * p + 1][1] = r3;
                    ldsm4(st + 3 * TILE_SZ + bRowOff[p] + chB, r0, r1, r2, r3);
                    bl[2 * p][0] = r0; bl[2 * p][1] = r1;
                    bl[2 * p + 1][0] = r2; bl[2 * p + 1][1] = r3;
                }
#pragma unroll
                for (int mi = 0; mi < 4; mi++)
#pragma unroll
                    for (int ni = 0; ni < 4; ni++) {
                        hmma_bf16(acc[mi][ni], ah[mi][0], ah[mi][1], ah[mi][2], ah[mi][3],
                                  bh[ni][0], bh[ni][1]);
                        hmma_bf16(acc[mi][ni], ah[mi][0], ah[mi][1], ah[mi][2], ah[mi][3],
                                  bl[ni][0], bl[ni][1]);
                        hmma_bf16(acc[mi][ni], al[mi][0], al[mi][1], al[mi][2], al[mi][3],
                                  bh[ni][0], bh[ni][1]);
                    }
            } else {
                uint32_t ah[4][4];
#pragma unroll
                for (int mi = 0; mi < 4; mi++)
                    ldsm4(st + aRowOff[mi] + chA,
                          ah[mi][0], ah[mi][1], ah[mi][2], ah[mi][3]);
                uint32_t bh[4][2];
#pragma unroll
                for (int p = 0; p < 2; p++) {
                    uint32_t r0, r1, r2, r3;
                    ldsm4(st + TILE_SZ + bRowOff[p] + chB, r0, r1, r2, r3);
                    bh[2 * p][0] = r0; bh[2 * p][1] = r1;
                    bh[2 * p + 1][0] = r2; bh[2 * p + 1][1] = r3;
                }
#pragma unroll
                for (int mi = 0; mi < 4; mi++)
#pragma unroll
                    for (int ni = 0; ni < 4; ni++)
                        hmma_fp16(acc[mi][ni], ah[mi][0], ah[mi][1], ah[mi][2], ah[mi][3],
                                  bh[ni][0], bh[ni][1]);
            }
        }

        __syncthreads();
        if (c + 2 < C) {
            uint32_t stn = sbase + (uint32_t)(c & 1) * STG;
            ll k0 = (ll)(c + 2) * 64;
            tile_cp(Ah, lda, m0, k0, stn, tid);
            tile_cp(Bh, ldb, n0, k0, stn + B_OFF, tid);
            if (MODE == 0) {
                tile_cp(Al, lda, m0, k0, stn + TILE_SZ, tid);
                tile_cp(Bl, ldb, n0, k0, stn + 3 * TILE_SZ, tid);
            }
            CP_COMMIT();
        }
    }

    // ---- Epilogue: acc -> smem staging -> coalesced global ----
    float* ep = (float*)smem;
    {
        int gr = lane >> 2, gc = lane & 3;
#pragma unroll
        for (int mi = 0; mi < 4; mi++)
#pragma unroll
            for (int ni = 0; ni < 4; ni++) {
                int row = wm * 64 + mi * 16 + gr;
                int col = wn * 32 + ni * 8 + gc * 2;
                float2 v0 = make_float2(acc[mi][ni][0], acc[mi][ni][1]);
                float2 v1 = make_float2(acc[mi][ni][2], acc[mi][ni][3]);
                *(float2*)&ep[row * EP_PITCH + col] = v0;
                *(float2*)&ep[(row + 8) * EP_PITCH + col] = v1;
            }
    }
    __syncthreads();

    {
        int lc = tid & 31;        // col group (x4)
        int rbase = tid >> 5;     // 0..7
        float4 bv = make_float4(0.f, 0.f, 0.f, 0.f);
        if (bias) bv = *(const float4*)(bias + n0 + lc * 4);
#pragma unroll
        for (int i = 0; i < 16; i++) {
            int row = rbase + i * 8;
            float4 v = *(float4*)&ep[row * EP_PITCH + lc * 4];
            v.x += bv.x; v.y += bv.y; v.z += bv.z; v.w += bv.w;
            ll off = coff + (ll)row * ldc + lc * 4;
            if (Cf) *(float4*)(Cf + off) = v;
            if (Chi) {
                __nv_bfloat16 h0 = __float2bfloat16(v.x);
                __nv_bfloat16 h1 = __float2bfloat16(v.y);
                __nv_bfloat16 h2 = __float2bfloat16(v.z);
                __nv_bfloat16 h3 = __float2bfloat16(v.w);
                __nv_bfloat16 l0 = __float2bfloat16(v.x - __bfloat162float(h0));
                __nv_bfloat16 l1 = __float2bfloat16(v.y - __bfloat162float(h1));
                __nv_bfloat16 l2 = __float2bfloat16(v.z - __bfloat162float(h2));
                __nv_bfloat16 l3 = __float2bfloat16(v.w - __bfloat162float(h3));
                uint2 hv, lv;
                __nv_bfloat16* hp = (__nv_bfloat16*)&hv;
                __nv_bfloat16* lp = (__nv_bfloat16*)&lv;
                hp[0] = h0; hp[1] = h1; hp[2] = h2; hp[3] = h3;
                lp[0] = l0; lp[1] = l1; lp[2] = l2; lp[3] = l3;
                *(uint2*)(Chi + off) = hv;
                *(uint2*)(Clo + off) = lv;
            }
        }
    }
}

// ---------------------------------------------------------------------------
// Fold BN into weights, output split bf16: Wf = W*scale, bias = W . shift
// ---------------------------------------------------------------------------
__global__ void fold_kernel(const float* __restrict__ W,
                            const float* __restrict__ gamma,
                            const float* __restrict__ beta,
                            const float* __restrict__ mean,
                            const float* __restrict__ var,
                            __nv_bfloat16* __restrict__ Whi,
                            __nv_bfloat16* __restrict__ Wlo,
                            float* __restrict__ bias, int D)
{
    int o = blockIdx.x;
    int tid = threadIdx.x;
    float partial = 0.f;
    const float* wrow = W + (ll)o * D;
    __nv_bfloat16* whr = Whi + (ll)o * D;
    __nv_bfloat16* wlr = Wlo + (ll)o * D;
    for (int d = tid; d < D; d += blockDim.x) {
        float sc = gamma[d] * rsqrtf(var[d] + 1e-5f);
        float sh = beta[d] - mean[d] * sc;
        float w = wrow[d];
        float wf = w * sc;
        __nv_bfloat16 hi = __float2bfloat16(wf);
        whr[d] = hi;
        wlr[d] = __float2bfloat16(wf - __bfloat162float(hi));
        partial += w * sh;
    }
    __shared__ float red[256];
    red[tid] = partial;
    __syncthreads();
    for (int s = 128; s > 0; s >>= 1) {
        if (tid < s) red[tid] += red[tid + s];
        __syncthreads();
    }
    if (tid == 0) bias[o] = red[0];
}

// ---------------------------------------------------------------------------
// Elementwise fp32 -> bf16 hi/lo split
// ---------------------------------------------------------------------------
__global__ void __launch_bounds__(256)
split_kernel(const float* __restrict__ x, __nv_bfloat16* __restrict__ hi,
             __nv_bfloat16* __restrict__ lo, ll n4)
{
    ll i = (ll)blockIdx.x * 256 + threadIdx.x;
    if (i >= n4) return;
    float4 v = *(const float4*)(x + i * 4);
    __nv_bfloat16 h0 = __float2bfloat16(v.x);
    __nv_bfloat16 h1 = __float2bfloat16(v.y);
    __nv_bfloat16 h2 = __float2bfloat16(v.z);
    __nv_bfloat16 h3 = __float2bfloat16(v.w);
    uint2 hv, lv;
    __nv_bfloat16* hp = (__nv_bfloat16*)&hv;
    __nv_bfloat16* lp = (__nv_bfloat16*)&lv;
    hp[0] = h0; hp[1] = h1; hp[2] = h2; hp[3] = h3;
    lp[0] = __float2bfloat16(v.x - __bfloat162float(h0));
    lp[1] = __float2bfloat16(v.y - __bfloat162float(h1));
    lp[2] = __float2bfloat16(v.z - __bfloat162float(h2));
    lp[3] = __float2bfloat16(v.w - __bfloat162float(h3));
    *(uint2*)(hi + i * 4) = hv;
    *(uint2*)(lo + i * 4) = lv;
}

// ---------------------------------------------------------------------------
// Per-batch transpose of h: ht[b][d][k] = h[b][k][d], fp16.
// ---------------------------------------------------------------------------
__global__ void __launch_bounds__(256)
transpose_f16(const float* __restrict__ h, __half* __restrict__ tf)
{
    __shared__ float t[32][33];
    int b = blockIdx.z;
    int k0 = blockIdx.x * 32;
    int d0 = blockIdx.y * 32;
    const float* hb = h + (ll)b * TK * D_;
#pragma unroll
    for (int j = 0; j < 4; j++) {
        int k = threadIdx.y + j * 8;
        t[k][threadIdx.x] = hb[(ll)(k0 + k) * D_ + d0 + threadIdx.x];
    }
    __syncthreads();
    __half* tb = tf + (ll)b * D_ * TK;
#pragma unroll
    for (int j = 0; j < 4; j++) {
        int d = threadIdx.y + j * 8;
        tb[(ll)(d0 + d) * TK + k0 + threadIdx.x] = __float2half(t[threadIdx.x][d]);
    }
}

// ---------------------------------------------------------------------------
// Row softmax in place + fp16 copy.
// ---------------------------------------------------------------------------
__global__ void __launch_bounds__(256)
softmax_kernel(float* __restrict__ a, __half* __restrict__ af16)
{
    ll rbase = (ll)blockIdx.x * TK;
    float* row = a + rbase;
    int tid = threadIdx.x;
    float x[4];
    float mx = -INFINITY;
#pragma unroll
    for (int i = 0; i < 4; i++) {
        x[i] = row[tid + 256 * i];
        mx = fmaxf(mx, x[i]);
    }
    __shared__ float red[256];
    red[tid] = mx;
    __syncthreads();
    for (int s = 128; s > 0; s >>= 1) {
        if (tid < s) red[tid] = fmaxf(red[tid], red[tid + s]);
        __syncthreads();
    }
    mx = red[0];
    __syncthreads();
    float sum = 0.f;
#pragma unroll
    for (int i = 0; i < 4; i++) {
        x[i] = expf(x[i] - mx);
        sum += x[i];
    }
    red[tid] = sum;
    __syncthreads();
    for (int s = 128; s > 0; s >>= 1) {
        if (tid < s) red[tid] += red[tid + s];
        __syncthreads();
    }
    float inv = 1.f / red[0];
#pragma unroll
    for (int i = 0; i < 4; i++) {
        float p = x[i] * inv;
        row[tid + 256 * i] = p;
        af16[rbase + tid + 256 * i] = __float2half(p);
    }
}

// ---------------------------------------------------------------------------
extern "C" void kernel_launch(void* const* d_in, const int* in_sizes, int n_in,
                              void* d_out, int out_size)
{
    const float* s_in      = (const float*)d_in[0];
    const float* h_in      = (const float*)d_in[1];
    const float* phi_gamma = (const float*)d_in[2];
    const float* phi_beta  = (const float*)d_in[3];
    const float* phi_mean  = (const float*)d_in[4];
    const float* phi_var   = (const float*)d_in[5];
    const float* W_phi     = (const float*)d_in[6];
    const float* psi_gamma = (const float*)d_in[7];
    const float* psi_beta  = (const float*)d_in[8];
    const float* psi_mean  = (const float*)d_in[9];
    const float* psi_var   = (const float*)d_in[10];
    const float* W_psi     = (const float*)d_in[11];
    const float* red_gamma = (const float*)d_in[12];
    const float* red_beta  = (const float*)d_in[13];
    const float* red_mean  = (const float*)d_in[14];
    const float* red_var   = (const float*)d_in[15];
    const float* W_red     = (const float*)d_in[16];

    float* a_out = (float*)d_out;               // [H, B, Tq, Tk]
    float* c_out = a_out + A_ELEMS;             // [B, Tq, D]

    __nv_bfloat16 *s_hi, *s_lo, *h_hi, *h_lo;
    __nv_bfloat16 *ms_hi, *ms_lo, *mh_hi, *mh_lo, *ctx_hi, *ctx_lo;
    __nv_bfloat16 *Wphi_hi, *Wphi_lo, *Wpsi_hi, *Wpsi_lo, *Wred_hi, *Wred_lo;
    __half *ht_f16, *a_f16;
    float *bphi, *bpsi, *bred;
    cudaGetSymbolAddress((void**)&s_hi, g_s_hi);   cudaGetSymbolAddress((void**)&s_lo, g_s_lo);
    cudaGetSymbolAddress((void**)&h_hi, g_h_hi);   cudaGetSymbolAddress((void**)&h_lo, g_h_lo);
    cudaGetSymbolAddress((void**)&ht_f16, g_ht_f16);
    cudaGetSymbolAddress((void**)&ms_hi, g_ms_hi); cudaGetSymbolAddress((void**)&ms_lo, g_ms_lo);
    cudaGetSymbolAddress((void**)&mh_hi, g_mh_hi); cudaGetSymbolAddress((void**)&mh_lo, g_mh_lo);
    cudaGetSymbolAddress((void**)&a_f16, g_a_f16);
    cudaGetSymbolAddress((void**)&ctx_hi, g_ctx_hi); cudaGetSymbolAddress((void**)&ctx_lo, g_ctx_lo);
    cudaGetSymbolAddress((void**)&Wphi_hi, g_Wphi_hi); cudaGetSymbolAddress((void**)&Wphi_lo, g_Wphi_lo);
    cudaGetSymbolAddress((void**)&Wpsi_hi, g_Wpsi_hi); cudaGetSymbolAddress((void**)&Wpsi_lo, g_Wpsi_lo);
    cudaGetSymbolAddress((void**)&Wred_hi, g_Wred_hi); cudaGetSymbolAddress((void**)&Wred_lo, g_Wred_lo);
    cudaGetSymbolAddress((void**)&bphi, g_bphi);
    cudaGetSymbolAddress((void**)&bpsi, g_bpsi);
    cudaGetSymbolAddress((void**)&bred, g_bred);

    cudaFuncSetAttribute(gemm_tc<0>, cudaFuncAttributeMaxDynamicSharedMemorySize,
                         SMEM_MODE0);
    cudaFuncSetAttribute(gemm_tc<1>, cudaFuncAttributeMaxDynamicSharedMemorySize,
                         SMEM_MODE1);

    // 1. BN folding (split bf16 weights) + input conversions
    fold_kernel<<<HP, 256>>>(W_phi, phi_gamma, phi_beta, phi_mean, phi_var,
                             Wphi_hi, Wphi_lo, bphi, D_);
    fold_kernel<<<PROJ, 256>>>(W_psi, psi_gamma, psi_beta, psi_mean, psi_var,
                               Wpsi_hi, Wpsi_lo, bpsi, D_);
    fold_kernel<<<D_, 256>>>(W_red, red_gamma, red_beta, red_mean, red_var,
                             Wred_hi, Wred_lo, bred, HD);
    split_kernel<<<(int)(((ll)B_ * TQ * D_ / 4 + 255) / 256), 256>>>(
        s_in, s_hi, s_lo, (ll)B_ * TQ * D_ / 4);
    split_kernel<<<(int)(((ll)B_ * TK * D_ / 4 + 255) / 256), 256>>>(
        h_in, h_hi, h_lo, (ll)B_ * TK * D_ / 4);
    transpose_f16<<<dim3(TK / 32, D_ / 32, B_), dim3(32, 8)>>>(h_in, ht_f16);

    // 2. ms = s @ Wphi^T + bphi  (M=8192, N=2048, K=512) -> split out
    gemm_tc<0><<<dim3(HP / 128, (B_ * TQ) / 128, 1), 256, SMEM_MODE0>>>(
        s_hi, s_lo, Wphi_hi, Wphi_lo, bphi,
        nullptr, ms_hi, ms_lo,
        D_, D_, D_, HP,
        1, 0, 0, 0, 0, 0, 0);

    // 3. mh = h @ Wpsi^T + bpsi  (M=32768, N=512, K=512) -> split out
    gemm_tc<0><<<dim3(PROJ / 128, (B_ * TK) / 128, 1), 256, SMEM_MODE0>>>(
        h_hi, h_lo, Wpsi_hi, Wpsi_lo, bpsi,
        nullptr, mh_hi, mh_lo,
        D_, D_, D_, PROJ,
        1, 0, 0, 0, 0, 0, 0);

    // 4. logits e[h,b,q,k] = ms4[b,q,h,:] . mh[b,k,:]  -> fp32 into a_out
    gemm_tc<0><<<dim3(TK / 128, TQ / 128, B_ * NH), 256, SMEM_MODE0>>>(
        ms_hi, ms_lo, mh_hi, mh_lo, nullptr,
        a_out, nullptr, nullptr,
        PROJ, HP, PROJ, TK,
        NH,
        (ll)TQ * HP, (ll)PROJ,
        (ll)TK * PROJ, 0,
        (ll)TQ * TK, (ll)B_ * TQ * TK);

    // 5. softmax (in place) + fp16 copy
    softmax_kernel<<<NH * B_ * TQ, 256>>>(a_out, a_f16);

    // 6. ctx[b,q,h*D+d] = a[h,b,q,:] . ht[b,d,:]  (fp16 single-pass) -> split out
    gemm_tc<1><<<dim3(D_ / 128, TQ / 128, B_ * NH), 256, SMEM_MODE1>>>(
        (const __nv_bfloat16*)a_f16, nullptr,
        (const __nv_bfloat16*)ht_f16, nullptr, nullptr,
        nullptr, ctx_hi, ctx_lo,
        TK, TK, TK, HD,
        NH,
        (ll)TQ * TK, (ll)B_ * TQ * TK,
        (ll)D_ * TK, 0,
        (ll)TQ * HD, (ll)D_);

    // 7. c = ctx @ Wred^T + bred  (M=8192, N=512, K=2048) -> fp32 out
    gemm_tc<0><<<dim3(D_ / 128, (B_ * TQ) / 128, 1), 256, SMEM_MODE0>>>(
        ctx_hi, ctx_lo, Wred_hi, Wred_lo, bred,
        c_out, nullptr, nullptr,
        HD, HD, HD, D_,
        1, 0, 0, 0, 0, 0, 0);
}